// round 4
// baseline (speedup 1.0000x reference)
#include <cuda_runtime.h>
#include <cstdint>
#include <math.h>

#define DIM      128
#define NPARAMS  8384
#define NT       512            // 16 warps

#define RS       132            // smem row stride in floats

// smem float offsets
#define OFF_L    0                 // L (perm layout) / Sigma staging: 128*132
#define OFF_EPS  (128 * RS)        // eps, perm layout, 128
#define OFF_LD   (OFF_EPS + 128)   // log-diag, 128
#define OFF_T    (OFF_LD + 128)    // per-row kl terms, 128
#define SMEM_FLOATS (OFF_T + 128)

// Column permutation: within each 8-wide k-group, store k at position
// 2*(k%4) + (k/4)  ->  (k, k+4) adjacent (one LDS.64 per mma fragment pair).
__device__ __forceinline__ int permcol(int j) {
    return (j & ~7) | (((j & 3) << 1) | ((j >> 2) & 1));
}

// Per-warp tile table: up to 3 m16n16 lower-triangle tiles, (mt<<4)|nt.
// Cost of tile = 4*(nt+1) mma; loads balanced: w0-w11 = 32, w12-14 = 28, w15 = 12.
__constant__ uint8_t TILE_TAB[16][3] = {
    {0x77, 0xFF, 0xFF},
    {0x76, 0x00, 0xFF},
    {0x66, 0x10, 0xFF},
    {0x75, 0x11, 0xFF},
    {0x65, 0x21, 0xFF},
    {0x55, 0x31, 0xFF},
    {0x74, 0x22, 0xFF},
    {0x64, 0x32, 0xFF},
    {0x54, 0x42, 0xFF},
    {0x44, 0x52, 0xFF},
    {0x73, 0x62, 0x20},
    {0x63, 0x72, 0x30},
    {0x53, 0x41, 0x40},
    {0x43, 0x51, 0x50},
    {0x33, 0x61, 0x60},
    {0x71, 0x70, 0xFF},
};

__device__ __forceinline__ void mma_tf32(float* d, uint32_t a0, uint32_t a1,
                                         uint32_t a2, uint32_t a3,
                                         uint32_t b0, uint32_t b1) {
    asm volatile(
        "mma.sync.aligned.m16n8k8.row.col.f32.tf32.tf32.f32 "
        "{%0,%1,%2,%3}, {%4,%5,%6,%7}, {%8,%9}, {%0,%1,%2,%3};"
        : "+f"(d[0]), "+f"(d[1]), "+f"(d[2]), "+f"(d[3])
        : "r"(a0), "r"(a1), "r"(a2), "r"(a3), "r"(b0), "r"(b1));
}

__global__ __launch_bounds__(NT, 2)
void fld_mma_kernel(const float* __restrict__ params,
                    const float* __restrict__ eps,
                    float* __restrict__ sample,
                    float* __restrict__ kl,
                    float* __restrict__ sigma)
{
    extern __shared__ float smf[];

    const int b   = blockIdx.x;
    const int tid = threadIdx.x;
    const int wid = tid >> 5;
    const int lid = tid & 31;
    const int gr  = lid >> 2;       // octet id 0..7
    const int tg  = lid & 3;        // thread-in-quad 0..3
    const float* P = params + (size_t)b * NPARAMS;

    if (tid < DIM)
        smf[OFF_EPS + permcol(tid)] = eps[(size_t)b * DIM + tid];

    // ---- Build L (tf32-rounded) into perm-layout smem ----
    // Packed: L_flat[p], p=i*128+j: p<8128 -> params[256+p]; else params[16511-p]
    // diag: exp(raw) (raw kept in s_ld); off-diag: raw * rsqrt(i+1); upper: 0
    #pragma unroll
    for (int q = 0; q < (DIM * DIM) / NT; q++) {
        int p = tid + q * NT;
        int i = p >> 7;
        int j = p & 127;
        float v = 0.0f;
        if (j <= i) {
            float raw = (p < 8128) ? P[256 + p] : P[16511 - p];
            if (i == j) {
                smf[OFF_LD + i] = raw;
                v = expf(raw);
            } else {
                v = raw * rsqrtf((float)(i + 1));
            }
        }
        uint32_t tv;
        asm("cvt.rna.tf32.f32 %0, %1;" : "=r"(tv) : "f"(v));
        *(uint32_t*)&smf[OFF_L + i * RS + permcol(j)] = tv;
    }
    __syncthreads();

    // ---- Sigma = L * L^T: lower m16n16 tiles only, k truncated per tile ----
    float acc[3][2][4];
    int   tmt[3], tnt[3];
    #pragma unroll
    for (int t = 0; t < 3; t++) {
        #pragma unroll
        for (int s = 0; s < 2; s++)
            #pragma unroll
            for (int c = 0; c < 4; c++) acc[t][s][c] = 0.0f;
        uint8_t code = TILE_TAB[wid][t];
        tmt[t] = code >> 4;
        tnt[t] = code & 15;
        if (code == 0xFF) continue;

        const int m0 = tmt[t] * 16;
        const int n0 = tnt[t] * 16;
        const int ksteps = (tnt[t] + 1) * 2;   // k8-blocks

        const float* arow0 = smf + OFF_L + (size_t)(m0 + gr) * RS + 2 * tg;
        const float* arow1 = arow0 + 8 * RS;
        const float* brow0 = smf + OFF_L + (size_t)(n0 + gr) * RS + 2 * tg;
        const float* brow1 = brow0 + 8 * RS;

        #pragma unroll 2
        for (int ks = 0; ks < ksteps; ks++) {
            const int k0 = ks * 8;
            uint2 a02 = *(const uint2*)(arow0 + k0);   // A[gr][k], A[gr][k+4]
            uint2 a13 = *(const uint2*)(arow1 + k0);   // A[gr+8][k], ...
            uint2 b0  = *(const uint2*)(brow0 + k0);
            uint2 b1  = *(const uint2*)(brow1 + k0);
            mma_tf32(acc[t][0], a02.x, a13.x, a02.y, a13.y, b0.x, b0.y);
            mma_tf32(acc[t][1], a02.x, a13.x, a02.y, a13.y, b1.x, b1.y);
        }
    }

    // ---- sample = mean + L*eps ; kl terms. 4 threads per row. ----
    {
        const int row  = tid >> 2;       // 0..127
        const int part = tid & 3;        // 32-element slice
        float accs = 0.0f, sq = 0.0f;
        const float* Lr = smf + OFF_L + (size_t)row * RS + part * 32;
        const float* se = smf + OFF_EPS + part * 32;
        #pragma unroll
        for (int q = 0; q < 32; q += 4) {
            float4 lv = *(const float4*)(Lr + q);
            float4 ev = *(const float4*)(se + q);
            accs = fmaf(lv.x, ev.x, accs);
            accs = fmaf(lv.y, ev.y, accs);
            accs = fmaf(lv.z, ev.z, accs);
            accs = fmaf(lv.w, ev.w, accs);
            sq = fmaf(lv.x, lv.x, sq);
            sq = fmaf(lv.y, lv.y, sq);
            sq = fmaf(lv.z, lv.z, sq);
            sq = fmaf(lv.w, lv.w, sq);
        }
        accs += __shfl_xor_sync(0xffffffffu, accs, 1);
        sq   += __shfl_xor_sync(0xffffffffu, sq,   1);
        accs += __shfl_xor_sync(0xffffffffu, accs, 2);
        sq   += __shfl_xor_sync(0xffffffffu, sq,   2);
        if (part == 0) {
            float m = P[row];
            sample[(size_t)b * DIM + row] = m + accs;
            smf[OFF_T + row] = sq - 1.0f + m * m - 2.0f * smf[OFF_LD + row];
        }
    }

    __syncthreads();   // all L reads done; OFF_T ready

    // kl reduction (warp 0) — overlaps with staging stores below
    if (wid == 0) {
        float t = smf[OFF_T + lid] + smf[OFF_T + 32 + lid] +
                  smf[OFF_T + 64 + lid] + smf[OFF_T + 96 + lid];
        #pragma unroll
        for (int o = 16; o > 0; o >>= 1)
            t += __shfl_down_sync(0xffffffffu, t, o);
        if (lid == 0) kl[b] = 0.5f * t;
    }

    // ---- Stage D tiles (direct + mirrored transpose) into smem ----
    #pragma unroll
    for (int t = 0; t < 3; t++) {
        if (tmt[t] == 15) continue;    // 0xFF >> 4
        const int m0 = tmt[t] * 16;
        const int n0 = tnt[t] * 16;
        float* s0 = smf + OFF_L + (size_t)(m0 + gr) * RS + n0 + 2 * tg;
        float* s1 = s0 + 8 * RS;
        #pragma unroll
        for (int s = 0; s < 2; s++) {
            *(float2*)(s0 + s * 8) = make_float2(acc[t][s][0], acc[t][s][1]);
            *(float2*)(s1 + s * 8) = make_float2(acc[t][s][2], acc[t][s][3]);
        }
        if (tmt[t] != tnt[t]) {
            // transpose: staging[n0+8s+2tg+c][m0 + gr (+8)]
            #pragma unroll
            for (int s = 0; s < 2; s++) {
                float* c0 = smf + OFF_L + (size_t)(n0 + 8 * s + 2 * tg) * RS + m0 + gr;
                c0[0]          = acc[t][s][0];
                c0[RS]         = acc[t][s][1];
                c0[8]          = acc[t][s][2];
                c0[RS + 8]     = acc[t][s][3];
            }
        }
    }
    __syncthreads();

    // ---- Coalesced copy-out: staging -> Sigma ----
    {
        float* Sg = sigma + (size_t)b * DIM * DIM;
        #pragma unroll
        for (int q = 0; q < (DIM * DIM / 4) / NT; q++) {
            int tq  = tid + q * NT;
            int row = tq >> 5;
            int c4  = (tq & 31) << 2;
            float4 v = *(const float4*)(smf + OFF_L + (size_t)row * RS + c4);
            *(float4*)(Sg + (size_t)row * DIM + c4) = v;
        }
    }
}

extern "C" void kernel_launch(void* const* d_in, const int* in_sizes, int n_in,
                              void* d_out, int out_size)
{
    const float* params = (const float*)d_in[0];
    const float* eps    = (const float*)d_in[1];
    const int B = in_sizes[0] / NPARAMS;

    float* out    = (float*)d_out;
    float* sample = out;                       // B * 128
    float* kl     = out + (size_t)B * DIM;     // B
    float* sigma  = kl + B;                    // B * 128 * 128

    const int smem = SMEM_FLOATS * sizeof(float);
    cudaFuncSetAttribute(fld_mma_kernel,
                         cudaFuncAttributeMaxDynamicSharedMemorySize, smem);
    fld_mma_kernel<<<B, NT, smem>>>(params, eps, sample, kl, sigma);
}

// round 5
// speedup vs baseline: 1.0356x; 1.0356x over previous
#include <cuda_runtime.h>
#include <cstdint>
#include <math.h>

#define DIM      128
#define NPARAMS  8384
#define NT       256            // 8 warps

// Two-region triangular L layout (floats):
//  region A: rows 0-63, 64 cols, stride 68
//  region B: rows 64-127, 128 cols, stride 132
#define RS_A     68
#define RS_B     132
#define OFF_A    0
#define OFF_B    (64 * RS_A)            // 4352
#define OFF_EPS  (OFF_B + 64 * RS_B)    // 12800 (permuted eps)
#define OFF_LD   (OFF_EPS + 128)        // log-diag
#define OFF_MEAN (OFF_LD + 128)
#define OFF_DIAG (OFF_MEAN + 128)       // Sigma diagonal
#define OFF_RW   (OFF_DIAG + 128)       // rsqrt(i+1) table
#define SMEM_FLOATS (OFF_RW + 128)      // 13440 floats = 53760 B

// Column permutation: within each 8-wide k-group, col k stored at
// 2*(k%4) + (k/4)  ->  (k, k+4) adjacent (one LDS.64 per mma frag pair).
__device__ __forceinline__ int permcol(int j) {
    return (j & ~7) | (((j & 3) << 1) | ((j >> 2) & 1));
}

// Per-warp m16n16 lower-triangle tile lists, (mt<<4)|nt, 0xFF = end.
// MMA cost per tile = 4*(nt+1); each warp sums to 60 MMAs.
__constant__ uint8_t TILE_TAB[8][8] = {
    {0x77, 0x43, 0x11, 0x00, 0xFF, 0xFF, 0xFF, 0xFF},
    {0x66, 0x54, 0x21, 0x30, 0xFF, 0xFF, 0xFF, 0xFF},
    {0x76, 0x44, 0x22, 0xFF, 0xFF, 0xFF, 0xFF, 0xFF},
    {0x55, 0x65, 0x32, 0xFF, 0xFF, 0xFF, 0xFF, 0xFF},
    {0x75, 0x64, 0x33, 0xFF, 0xFF, 0xFF, 0xFF, 0xFF},
    {0x74, 0x53, 0x31, 0x41, 0x20, 0x40, 0xFF, 0xFF},
    {0x63, 0x73, 0x42, 0x52, 0x10, 0xFF, 0xFF, 0xFF},
    {0x62, 0x72, 0x51, 0x61, 0x71, 0x50, 0x60, 0x70},
};

__device__ __forceinline__ void mma_tf32(float* d, uint32_t a0, uint32_t a1,
                                         uint32_t a2, uint32_t a3,
                                         uint32_t b0, uint32_t b1) {
    asm volatile(
        "mma.sync.aligned.m16n8k8.row.col.f32.tf32.tf32.f32 "
        "{%0,%1,%2,%3}, {%4,%5,%6,%7}, {%8,%9}, {%0,%1,%2,%3};"
        : "+f"(d[0]), "+f"(d[1]), "+f"(d[2]), "+f"(d[3])
        : "r"(a0), "r"(a1), "r"(a2), "r"(a3), "r"(b0), "r"(b1));
}

__global__ __launch_bounds__(NT, 4)
void fld_mma_kernel(const float* __restrict__ params,
                    const float* __restrict__ eps,
                    float* __restrict__ sample,
                    float* __restrict__ kl,
                    float* __restrict__ sigma)
{
    extern __shared__ float smf[];

    const int b   = blockIdx.x;
    const int tid = threadIdx.x;
    const int wid = tid >> 5;
    const int lid = tid & 31;
    const int gr  = lid >> 2;       // octet row 0..7
    const int tg  = lid & 3;        // thread-in-quad 0..3
    const float* P = params + (size_t)b * NPARAMS;

    // ---- phase 0: tables, mean, eps ----
    if (tid < DIM) {
        smf[OFF_RW + tid]   = rsqrtf((float)(tid + 1));
        smf[OFF_MEAN + tid] = P[tid];
        smf[OFF_EPS + permcol(tid)] = eps[(size_t)b * DIM + tid];
    }
    __syncthreads();

    // ---- phase 1: unpack L (tf32) into two-region perm-layout smem ----
    // L_flat[p], p=i*128+j: p<8128 -> params[256+p]; else params[16511-p]
    // diag: exp(raw) (raw saved to s_ld); off-diag: raw * rsqrt(i+1)
    #pragma unroll 8
    for (int q = 0; q < (DIM * DIM) / NT; q++) {
        int p = tid + q * NT;
        int i = p >> 7;             // warp-uniform
        int j = p & 127;
        float v = 0.0f;
        if (j <= i) {
            float raw = (p < 8128) ? P[256 + p] : P[16511 - p];
            if (i == j) {
                smf[OFF_LD + i] = raw;
                v = expf(raw);
            } else {
                v = raw * smf[OFF_RW + i];
            }
        }
        if (i >= 64 || j < 64) {
            uint32_t tv;
            asm("cvt.rna.tf32.f32 %0, %1;" : "=r"(tv) : "f"(v));
            int base = (i < 64) ? (OFF_A + i * RS_A) : (OFF_B + (i - 64) * RS_B);
            *(uint32_t*)&smf[base + permcol(j)] = tv;
        }
    }
    __syncthreads();

    // ---- phase 2a: lower-triangle m16n16 tiles, direct+mirror stores ----
    float* Sg = sigma + (size_t)b * DIM * DIM;

    for (int t = 0; t < 8; t++) {
        uint32_t code = TILE_TAB[wid][t];
        if (code == 0xFF) break;
        const int mt = code >> 4, nt = code & 15;
        const int m0 = mt * 16, n0 = nt * 16;
        const int rs_m = (mt < 4) ? RS_A : RS_B;
        const int rs_n = (nt < 4) ? RS_A : RS_B;
        const int abase = ((mt < 4) ? (OFF_A + (m0 + gr) * RS_A)
                                    : (OFF_B + (m0 + gr - 64) * RS_B)) + 2 * tg;
        const int bbase = ((nt < 4) ? (OFF_A + (n0 + gr) * RS_A)
                                    : (OFF_B + (n0 + gr - 64) * RS_B)) + 2 * tg;
        const int ksteps = 2 * (nt + 1);

        float d[2][4];
        #pragma unroll
        for (int s = 0; s < 2; s++)
            #pragma unroll
            for (int c = 0; c < 4; c++) d[s][c] = 0.0f;

        #pragma unroll 2
        for (int ks = 0; ks < ksteps; ks++) {
            const int k0 = ks * 8;
            uint2 a02 = *(const uint2*)(smf + abase + k0);
            uint2 a13 = *(const uint2*)(smf + abase + 8 * rs_m + k0);
            uint2 b0  = *(const uint2*)(smf + bbase + k0);
            uint2 b1  = *(const uint2*)(smf + bbase + 8 * rs_n + k0);
            mma_tf32(d[0], a02.x, a13.x, a02.y, a13.y, b0.x, b0.y);
            mma_tf32(d[1], a02.x, a13.x, a02.y, a13.y, b1.x, b1.y);
        }

        // direct stores (rows m0.., cols n0..)
        #pragma unroll
        for (int s = 0; s < 2; s++) {
            int col = n0 + 8 * s + 2 * tg;
            *(float2*)&Sg[(size_t)(m0 + gr) * DIM + col]     = make_float2(d[s][0], d[s][1]);
            *(float2*)&Sg[(size_t)(m0 + gr + 8) * DIM + col] = make_float2(d[s][2], d[s][3]);
        }

        if (mt != nt) {
            // mirrored transpose via xor-4 shuffles -> float2 stores
            const int odd  = gr & 1;
            const int colt = m0 + (gr & ~1);
            #pragma unroll
            for (int s = 0; s < 2; s++) {
                float q0 = __shfl_xor_sync(0xffffffffu, d[s][0], 4);
                float q1 = __shfl_xor_sync(0xffffffffu, d[s][1], 4);
                float q2 = __shfl_xor_sync(0xffffffffu, d[s][2], 4);
                float q3 = __shfl_xor_sync(0xffffffffu, d[s][3], 4);
                int rowt = n0 + 8 * s + 2 * tg + odd;
                float2 w0 = odd ? make_float2(q1, d[s][1]) : make_float2(d[s][0], q0);
                float2 w1 = odd ? make_float2(q3, d[s][3]) : make_float2(d[s][2], q2);
                *(float2*)&Sg[(size_t)rowt * DIM + colt]     = w0;
                *(float2*)&Sg[(size_t)rowt * DIM + colt + 8] = w1;
            }
        } else if (2 * tg == (gr & ~1)) {
            // Sigma diagonal: row m0+gr -> d[0][gr&1], row m0+gr+8 -> d[1][2+(gr&1)]
            int c = gr & 1;
            smf[OFF_DIAG + m0 + gr]     = d[0][c];
            smf[OFF_DIAG + m0 + gr + 8] = d[1][2 + c];
        }
    }

    // ---- phase 2b: sample = mean + L*eps (2 threads per row) ----
    {
        const int r = tid >> 1;
        const int h = tid & 1;
        float dot = 0.0f;
        if (r >= 64 || h == 0) {
            const int base = ((r < 64) ? (OFF_A + r * RS_A)
                                       : (OFF_B + (r - 64) * RS_B)) + h * 64;
            const float4* Lp = (const float4*)(smf + base);
            const float4* Ep = (const float4*)(smf + OFF_EPS + h * 64);
            #pragma unroll
            for (int q = 0; q < 16; q++) {
                float4 lv = Lp[q], ev = Ep[q];
                dot = fmaf(lv.x, ev.x, dot);
                dot = fmaf(lv.y, ev.y, dot);
                dot = fmaf(lv.z, ev.z, dot);
                dot = fmaf(lv.w, ev.w, dot);
            }
        }
        dot += __shfl_xor_sync(0xffffffffu, dot, 1);
        if (h == 0)
            sample[(size_t)b * DIM + r] = smf[OFF_MEAN + r] + dot;
    }
    __syncthreads();   // s_diag complete

    // ---- phase 3: kl (warp 0) ----
    if (wid == 0) {
        float t = 0.0f;
        #pragma unroll
        for (int k = 0; k < 4; k++) {
            int r = lid + 32 * k;
            float m = smf[OFF_MEAN + r];
            t += smf[OFF_DIAG + r] - 1.0f + m * m - 2.0f * smf[OFF_LD + r];
        }
        #pragma unroll
        for (int o = 16; o > 0; o >>= 1)
            t += __shfl_down_sync(0xffffffffu, t, o);
        if (lid == 0) kl[b] = 0.5f * t;
    }
}

extern "C" void kernel_launch(void* const* d_in, const int* in_sizes, int n_in,
                              void* d_out, int out_size)
{
    const float* params = (const float*)d_in[0];
    const float* eps    = (const float*)d_in[1];
    const int B = in_sizes[0] / NPARAMS;

    float* out    = (float*)d_out;
    float* sample = out;                       // B * 128
    float* kl     = out + (size_t)B * DIM;     // B
    float* sigma  = kl + B;                    // B * 128 * 128

    const int smem = SMEM_FLOATS * sizeof(float);
    cudaFuncSetAttribute(fld_mma_kernel,
                         cudaFuncAttributeMaxDynamicSharedMemorySize, smem);
    fld_mma_kernel<<<B, NT, smem>>>(params, eps, sample, kl, sigma);
}

// round 6
// speedup vs baseline: 2.1675x; 2.0930x over previous
#include <cuda_runtime.h>
#include <cstdint>
#include <math.h>

#define DIM      128
#define NPARAMS  8384
#define NT       256            // 8 warps

// Two-region triangular L layout (floats), plain row-major columns:
//  region A: rows 0-63, 64 cols, stride 68
//  region B: rows 64-127, 128 cols, stride 132
#define RS_A     68
#define RS_B     132
#define OFF_A    0
#define OFF_B    (64 * RS_A)            // 4352
#define OFF_EPS  (OFF_B + 64 * RS_B)    // 12800
#define OFF_LD   (OFF_EPS + 128)
#define OFF_MEAN (OFF_LD + 128)
#define OFF_DIAG (OFF_MEAN + 128)
#define SMEM_FLOATS (OFF_DIAG + 128)    // 13312 floats = 53248 B

// Per-warp m16n16 lower-triangle tile lists, (mt<<4)|nt, 0xFF = end.
// MMA cost per tile = 4*(nt+1); each warp sums to 60 MMAs.
__constant__ uint8_t TILE_TAB[8][8] = {
    {0x77, 0x43, 0x11, 0x00, 0xFF, 0xFF, 0xFF, 0xFF},
    {0x66, 0x54, 0x21, 0x30, 0xFF, 0xFF, 0xFF, 0xFF},
    {0x76, 0x44, 0x22, 0xFF, 0xFF, 0xFF, 0xFF, 0xFF},
    {0x55, 0x65, 0x32, 0xFF, 0xFF, 0xFF, 0xFF, 0xFF},
    {0x75, 0x64, 0x33, 0xFF, 0xFF, 0xFF, 0xFF, 0xFF},
    {0x74, 0x53, 0x31, 0x41, 0x20, 0x40, 0xFF, 0xFF},
    {0x63, 0x73, 0x42, 0x52, 0x10, 0xFF, 0xFF, 0xFF},
    {0x62, 0x72, 0x51, 0x61, 0x71, 0x50, 0x60, 0x70},
};

__device__ __forceinline__ int rowbase(int r) {
    return (r < 64) ? (OFF_A + r * RS_A) : (OFF_B + (r - 64) * RS_B);
}

__device__ __forceinline__ void mma_tf32(float* d, uint32_t a0, uint32_t a1,
                                         uint32_t a2, uint32_t a3,
                                         uint32_t b0, uint32_t b1) {
    asm volatile(
        "mma.sync.aligned.m16n8k8.row.col.f32.tf32.tf32.f32 "
        "{%0,%1,%2,%3}, {%4,%5,%6,%7}, {%8,%9}, {%0,%1,%2,%3};"
        : "+f"(d[0]), "+f"(d[1]), "+f"(d[2]), "+f"(d[3])
        : "r"(a0), "r"(a1), "r"(a2), "r"(a3), "r"(b0), "r"(b1));
}

__device__ __forceinline__ uint32_t to_tf32(float v) {
    uint32_t t;
    asm("cvt.rna.tf32.f32 %0, %1;" : "=r"(t) : "f"(v));
    return t;
}

__global__ __launch_bounds__(NT, 4)
void fld_mma_kernel(const float* __restrict__ params,
                    const float* __restrict__ eps,
                    float* __restrict__ sample,
                    float* __restrict__ kl,
                    float* __restrict__ sigma)
{
    extern __shared__ float smf[];

    const int b   = blockIdx.x;
    const int tid = threadIdx.x;
    const int wid = tid >> 5;
    const int lid = tid & 31;
    const int gr  = lid >> 2;       // octet row 0..7
    const int tg  = lid & 3;        // thread-in-quad 0..3
    const float* P = params + (size_t)b * NPARAMS;

    // ---- phase 0: mean, eps (plain layout) ----
    if (tid < DIM) {
        smf[OFF_MEAN + tid] = P[tid];
        smf[OFF_EPS + tid]  = eps[(size_t)b * DIM + tid];
    }

    // ---- phase 1: vectorized triangular unpack ----
    // Row r sources are contiguous: r<64 -> P[256+128r+j] ascending;
    // r>=64 -> P[16511-128r-j] descending (float4 + register reverse).
    // Thread pair (2u, 2u+1) owns row r; halves split the row's float4 chunks.
    // Rows interleaved big/small for warp balance.
    const int u = tid >> 1, h = tid & 1;
    const int r = (u & 1) ? (127 - (u >> 1)) : (u >> 1);
    const float rw = rsqrtf((float)(r + 1));
    const int c4tot = (r >> 2) + 1;          // chunks covering j=0..r
    const int ch0   = (c4tot + 1) >> 1;
    const int cbeg  = h ? ch0 : 0;
    const int cend  = h ? c4tot : ch0;
    const int rbase = rowbase(r);

    for (int c = cbeg; c < cend; c++) {
        const int j0 = c << 2;
        float4 v;
        if (r < 64) {
            v = *(const float4*)(P + 256 + 128 * r + j0);
        } else {
            float4 w = *(const float4*)(P + 16508 - 128 * r - j0);
            v = make_float4(w.w, w.z, w.y, w.x);
        }
        if (j0 + 3 < r) {               // pure off-diagonal chunk
            v.x *= rw; v.y *= rw; v.z *= rw; v.w *= rw;
        } else {                        // chunk containing diag / pad
            float vv[4] = {v.x, v.y, v.z, v.w};
            #pragma unroll
            for (int e = 0; e < 4; e++) {
                int j = j0 + e;
                float raw = vv[e];
                if (j < r)       vv[e] = raw * rw;
                else if (j == r) { smf[OFF_LD + r] = raw; vv[e] = expf(raw); }
                else             vv[e] = 0.0f;
            }
            v = make_float4(vv[0], vv[1], vv[2], vv[3]);
        }
        uint4 t4 = make_uint4(to_tf32(v.x), to_tf32(v.y),
                              to_tf32(v.z), to_tf32(v.w));
        *(uint4*)&smf[rbase + j0] = t4;
    }
    if (h) {
        // zero-pad row tail to its 16-col boundary (all the GEMM reads)
        const int cb = ((r >> 4) + 1) << 2;
        for (int c = c4tot; c < cb; c++)
            *(float4*)&smf[rbase + (c << 2)] = make_float4(0.f, 0.f, 0.f, 0.f);
    }
    __syncthreads();

    // ---- phase 2a: lower-triangle m16n16 tiles, direct + mirror stores ----
    float* Sg = sigma + (size_t)b * DIM * DIM;

    for (int t = 0; t < 8; t++) {
        const uint32_t code = TILE_TAB[wid][t];
        if (code == 0xFF) break;
        const int mt = code >> 4, nt = code & 15;
        const int m0 = mt * 16, n0 = nt * 16;
        const int rs_m = (mt < 4) ? RS_A : RS_B;
        const int rs_n = (nt < 4) ? RS_A : RS_B;
        const int ar0 = rowbase(m0 + gr) + tg;
        const int ar1 = ar0 + 8 * rs_m;
        const int br0 = rowbase(n0 + gr) + tg;
        const int br1 = br0 + 8 * rs_n;
        const int ksteps = 2 * (nt + 1);

        float d[2][4];
        #pragma unroll
        for (int s = 0; s < 2; s++)
            #pragma unroll
            for (int c = 0; c < 4; c++) d[s][c] = 0.0f;

        #pragma unroll 2
        for (int ks = 0; ks < ksteps; ks++) {
            const int k0 = ks * 8;
            uint32_t a0 = *(const uint32_t*)&smf[ar0 + k0];
            uint32_t a2 = *(const uint32_t*)&smf[ar0 + k0 + 4];
            uint32_t a1 = *(const uint32_t*)&smf[ar1 + k0];
            uint32_t a3 = *(const uint32_t*)&smf[ar1 + k0 + 4];
            uint32_t b0x = *(const uint32_t*)&smf[br0 + k0];
            uint32_t b0y = *(const uint32_t*)&smf[br0 + k0 + 4];
            uint32_t b1x = *(const uint32_t*)&smf[br1 + k0];
            uint32_t b1y = *(const uint32_t*)&smf[br1 + k0 + 4];
            mma_tf32(d[0], a0, a1, a2, a3, b0x, b0y);
            mma_tf32(d[1], a0, a1, a2, a3, b1x, b1y);
        }

        // direct stores (rows m0.., cols n0..)
        #pragma unroll
        for (int s = 0; s < 2; s++) {
            int col = n0 + 8 * s + 2 * tg;
            *(float2*)&Sg[(size_t)(m0 + gr) * DIM + col]     = make_float2(d[s][0], d[s][1]);
            *(float2*)&Sg[(size_t)(m0 + gr + 8) * DIM + col] = make_float2(d[s][2], d[s][3]);
        }

        if (mt != nt) {
            // mirrored transpose via xor-4 shuffles -> float2 stores
            const int odd  = gr & 1;
            const int colt = m0 + (gr & ~1);
            #pragma unroll
            for (int s = 0; s < 2; s++) {
                float q0 = __shfl_xor_sync(0xffffffffu, d[s][0], 4);
                float q1 = __shfl_xor_sync(0xffffffffu, d[s][1], 4);
                float q2 = __shfl_xor_sync(0xffffffffu, d[s][2], 4);
                float q3 = __shfl_xor_sync(0xffffffffu, d[s][3], 4);
                int rowt = n0 + 8 * s + 2 * tg + odd;
                float2 w0 = odd ? make_float2(q1, d[s][1]) : make_float2(d[s][0], q0);
                float2 w1 = odd ? make_float2(q3, d[s][3]) : make_float2(d[s][2], q2);
                *(float2*)&Sg[(size_t)rowt * DIM + colt]     = w0;
                *(float2*)&Sg[(size_t)rowt * DIM + colt + 8] = w1;
            }
        } else if (2 * tg == (gr & ~1)) {
            // Sigma diagonal for kl
            int c = gr & 1;
            smf[OFF_DIAG + m0 + gr]     = d[0][c];
            smf[OFF_DIAG + m0 + gr + 8] = d[1][2 + c];
        }
    }

    // ---- phase 2b: sample = mean + L*eps (same chunk split as unpack) ----
    {
        float dot = 0.0f;
        for (int c = cbeg; c < cend; c++) {
            const int j0 = c << 2;
            float4 lv = *(const float4*)&smf[rbase + j0];
            float4 ev = *(const float4*)&smf[OFF_EPS + j0];
            dot = fmaf(lv.x, ev.x, dot);
            dot = fmaf(lv.y, ev.y, dot);
            dot = fmaf(lv.z, ev.z, dot);
            dot = fmaf(lv.w, ev.w, dot);
        }
        dot += __shfl_xor_sync(0xffffffffu, dot, 1);
        if (!h)
            sample[(size_t)b * DIM + r] = smf[OFF_MEAN + r] + dot;
    }
    __syncthreads();   // s_diag / s_ld complete

    // ---- phase 3: kl (warp 0) ----
    if (wid == 0) {
        float t = 0.0f;
        #pragma unroll
        for (int k = 0; k < 4; k++) {
            int rr = lid + 32 * k;
            float m = smf[OFF_MEAN + rr];
            t += smf[OFF_DIAG + rr] - 1.0f + m * m - 2.0f * smf[OFF_LD + rr];
        }
        #pragma unroll
        for (int o = 16; o > 0; o >>= 1)
            t += __shfl_down_sync(0xffffffffu, t, o);
        if (lid == 0) kl[b] = 0.5f * t;
    }
}

extern "C" void kernel_launch(void* const* d_in, const int* in_sizes, int n_in,
                              void* d_out, int out_size)
{
    const float* params = (const float*)d_in[0];
    const float* eps    = (const float*)d_in[1];
    const int B = in_sizes[0] / NPARAMS;

    float* out    = (float*)d_out;
    float* sample = out;                       // B * 128
    float* kl     = out + (size_t)B * DIM;     // B
    float* sigma  = kl + B;                    // B * 128 * 128

    const int smem = SMEM_FLOATS * sizeof(float);
    cudaFuncSetAttribute(fld_mma_kernel,
                         cudaFuncAttributeMaxDynamicSharedMemorySize, smem);
    fld_mma_kernel<<<B, NT, smem>>>(params, eps, sample, kl, sigma);
}

// round 7
// speedup vs baseline: 2.3864x; 1.1010x over previous
#include <cuda_runtime.h>
#include <cstdint>
#include <math.h>

#define DIM      128
#define NPARAMS  8384
#define NT       256            // 8 warps

// Two-region triangular L layout (floats), plain row-major columns:
//  region A: rows 0-63, 64 cols, stride 68
//  region B: rows 64-127, 128 cols, stride 132
#define RS_A     68
#define RS_B     132
#define OFF_A    0
#define OFF_B    (64 * RS_A)            // 4352
#define OFF_EPS  (OFF_B + 64 * RS_B)    // 12800
#define OFF_LD   (OFF_EPS + 128)
#define OFF_MEAN (OFF_LD + 128)
#define OFF_DIAG (OFF_MEAN + 128)
#define SMEM_FLOATS (OFF_DIAG + 128)    // 13312 floats = 53248 B

// Per-warp m16n16 lower-triangle tile lists, (mt<<4)|nt, 0xFF = end.
// MMA cost per tile = 4*(nt+1); each warp sums to 60 MMAs.
__constant__ uint8_t TILE_TAB[8][8] = {
    {0x77, 0x43, 0x11, 0x00, 0xFF, 0xFF, 0xFF, 0xFF},
    {0x66, 0x54, 0x21, 0x30, 0xFF, 0xFF, 0xFF, 0xFF},
    {0x76, 0x44, 0x22, 0xFF, 0xFF, 0xFF, 0xFF, 0xFF},
    {0x55, 0x65, 0x32, 0xFF, 0xFF, 0xFF, 0xFF, 0xFF},
    {0x75, 0x64, 0x33, 0xFF, 0xFF, 0xFF, 0xFF, 0xFF},
    {0x74, 0x53, 0x31, 0x41, 0x20, 0x40, 0xFF, 0xFF},
    {0x63, 0x73, 0x42, 0x52, 0x10, 0xFF, 0xFF, 0xFF},
    {0x62, 0x72, 0x51, 0x61, 0x71, 0x50, 0x60, 0x70},
};

__device__ __forceinline__ int rowbase(int r) {
    return (r < 64) ? (OFF_A + r * RS_A) : (OFF_B + (r - 64) * RS_B);
}

__device__ __forceinline__ void mma_tf32(float* d, uint32_t a0, uint32_t a1,
                                         uint32_t a2, uint32_t a3,
                                         uint32_t b0, uint32_t b1) {
    asm volatile(
        "mma.sync.aligned.m16n8k8.row.col.f32.tf32.tf32.f32 "
        "{%0,%1,%2,%3}, {%4,%5,%6,%7}, {%8,%9}, {%0,%1,%2,%3};"
        : "+f"(d[0]), "+f"(d[1]), "+f"(d[2]), "+f"(d[3])
        : "r"(a0), "r"(a1), "r"(a2), "r"(a3), "r"(b0), "r"(b1));
}

__device__ __forceinline__ uint32_t to_tf32(float v) {
    uint32_t t;
    asm("cvt.rna.tf32.f32 %0, %1;" : "=r"(t) : "f"(v));
    return t;
}

// Transform one float4 chunk of row r (cols j0..j0+3) and store (tf32) to smem.
// Chunks with j0 <= r carry data; j>r elements zeroed; diag -> exp, log saved.
__device__ __forceinline__ void xform_store(float* smf, const int rbase,
                                            const int r, const int j0,
                                            const float rw, float4 v,
                                            bool has_data) {
    if (!has_data) {
        v = make_float4(0.f, 0.f, 0.f, 0.f);
    } else if (j0 + 3 < r) {
        v.x *= rw; v.y *= rw; v.z *= rw; v.w *= rw;
    } else {
        float vv[4] = {v.x, v.y, v.z, v.w};
        #pragma unroll
        for (int e = 0; e < 4; e++) {
            int j = j0 + e;
            float raw = vv[e];
            if (j < r)       vv[e] = raw * rw;
            else if (j == r) { smf[OFF_LD + r] = raw; vv[e] = expf(raw); }
            else             vv[e] = 0.0f;
        }
        v = make_float4(vv[0], vv[1], vv[2], vv[3]);
    }
    *(uint4*)&smf[rbase + j0] =
        make_uint4(to_tf32(v.x), to_tf32(v.y), to_tf32(v.z), to_tf32(v.w));
}

__global__ __launch_bounds__(NT, 4)
void fld_mma_kernel(const float* __restrict__ params,
                    const float* __restrict__ eps,
                    float* __restrict__ sample,
                    float* __restrict__ kl,
                    float* __restrict__ sigma)
{
    extern __shared__ float smf[];

    const int b   = blockIdx.x;
    const int tid = threadIdx.x;
    const int wid = tid >> 5;
    const int lid = tid & 31;
    const int gr  = lid >> 2;       // octet row 0..7
    const int tg  = lid & 3;        // thread-in-quad 0..3
    const float* P = params + (size_t)b * NPARAMS;

    // ---- phase 0: mean, eps ----
    if (tid < DIM) {
        smf[OFF_MEAN + tid] = P[tid];
        smf[OFF_EPS + tid]  = eps[(size_t)b * DIM + tid];
    }

    // ---- phase 1: coalesced triangular unpack ----
    // Row sources are contiguous in params:
    //   r < 64 : P[256 + 128r + j], ascending
    //   r >= 64: P[16511 - 128r - j], descending (float4 + register reverse)
    // Rows >= 64: one row per warp per iteration (32 lanes x float4).
    #pragma unroll
    for (int q = 0; q < 8; q++) {
        const int r  = 64 + wid + 8 * q;
        const int j0 = lid << 2;
        const int cb = (r & ~15) + 16;          // exclusive col bound (GEMM reads)
        if (j0 < cb) {
            const float rw = rsqrtf((float)(r + 1));
            float4 v = make_float4(0.f, 0.f, 0.f, 0.f);
            const bool has = (j0 <= r);
            if (has) {
                float4 w4 = *(const float4*)(P + 16508 - 128 * r - j0);
                v = make_float4(w4.w, w4.z, w4.y, w4.x);
            }
            xform_store(smf, OFF_B + (r - 64) * RS_B, r, j0, rw, v, has);
        }
    }
    // Rows < 64: two rows per warp (half-warps), pairing small+large rows.
    #pragma unroll
    for (int q = 0; q < 4; q++) {
        const int hw = lid >> 4;                // 0: row rA, 1: row 63-rA
        const int hl = lid & 15;
        const int rA = wid + 8 * q;             // 0..31
        const int r  = hw ? (63 - rA) : rA;
        const int j0 = hl << 2;
        const int cb = (r & ~15) + 16;
        if (j0 < cb) {
            const float rw = rsqrtf((float)(r + 1));
            float4 v = make_float4(0.f, 0.f, 0.f, 0.f);
            const bool has = (j0 <= r);
            if (has)
                v = *(const float4*)(P + 256 + 128 * r + j0);
            xform_store(smf, OFF_A + r * RS_A, r, j0, rw, v, has);
        }
    }
    __syncthreads();

    // ---- phase 2a: lower-triangle m16n16 tiles, direct + mirror stores ----
    float* Sg = sigma + (size_t)b * DIM * DIM;

    for (int t = 0; t < 8; t++) {
        const uint32_t code = TILE_TAB[wid][t];
        if (code == 0xFF) break;
        const int mt = code >> 4, nt = code & 15;
        const int m0 = mt * 16, n0 = nt * 16;
        const int rs_m = (mt < 4) ? RS_A : RS_B;
        const int rs_n = (nt < 4) ? RS_A : RS_B;
        const int ar0 = rowbase(m0 + gr) + tg;
        const int ar1 = ar0 + 8 * rs_m;
        const int br0 = rowbase(n0 + gr) + tg;
        const int br1 = br0 + 8 * rs_n;
        const int ksteps = 2 * (nt + 1);

        float d[2][4];
        #pragma unroll
        for (int s = 0; s < 2; s++)
            #pragma unroll
            for (int c = 0; c < 4; c++) d[s][c] = 0.0f;

        if (mt == nt) {
            // diagonal tile: B fragments alias A fragments (same rows)
            #pragma unroll 2
            for (int ks = 0; ks < ksteps; ks++) {
                const int k0 = ks * 8;
                uint32_t a0 = *(const uint32_t*)&smf[ar0 + k0];
                uint32_t a2 = *(const uint32_t*)&smf[ar0 + k0 + 4];
                uint32_t a1 = *(const uint32_t*)&smf[ar1 + k0];
                uint32_t a3 = *(const uint32_t*)&smf[ar1 + k0 + 4];
                mma_tf32(d[0], a0, a1, a2, a3, a0, a2);
                mma_tf32(d[1], a0, a1, a2, a3, a1, a3);
            }
        } else {
            #pragma unroll 2
            for (int ks = 0; ks < ksteps; ks++) {
                const int k0 = ks * 8;
                uint32_t a0 = *(const uint32_t*)&smf[ar0 + k0];
                uint32_t a2 = *(const uint32_t*)&smf[ar0 + k0 + 4];
                uint32_t a1 = *(const uint32_t*)&smf[ar1 + k0];
                uint32_t a3 = *(const uint32_t*)&smf[ar1 + k0 + 4];
                uint32_t b0x = *(const uint32_t*)&smf[br0 + k0];
                uint32_t b0y = *(const uint32_t*)&smf[br0 + k0 + 4];
                uint32_t b1x = *(const uint32_t*)&smf[br1 + k0];
                uint32_t b1y = *(const uint32_t*)&smf[br1 + k0 + 4];
                mma_tf32(d[0], a0, a1, a2, a3, b0x, b0y);
                mma_tf32(d[1], a0, a1, a2, a3, b1x, b1y);
            }
        }

        // direct stores (rows m0.., cols n0..)
        #pragma unroll
        for (int s = 0; s < 2; s++) {
            int col = n0 + 8 * s + 2 * tg;
            *(float2*)&Sg[(size_t)(m0 + gr) * DIM + col]     = make_float2(d[s][0], d[s][1]);
            *(float2*)&Sg[(size_t)(m0 + gr + 8) * DIM + col] = make_float2(d[s][2], d[s][3]);
        }

        if (mt != nt) {
            // mirrored transpose via xor-4 shuffles -> float2 stores
            const int odd  = gr & 1;
            const int colt = m0 + (gr & ~1);
            #pragma unroll
            for (int s = 0; s < 2; s++) {
                float q0 = __shfl_xor_sync(0xffffffffu, d[s][0], 4);
                float q1 = __shfl_xor_sync(0xffffffffu, d[s][1], 4);
                float q2 = __shfl_xor_sync(0xffffffffu, d[s][2], 4);
                float q3 = __shfl_xor_sync(0xffffffffu, d[s][3], 4);
                int rowt = n0 + 8 * s + 2 * tg + odd;
                float2 w0 = odd ? make_float2(q1, d[s][1]) : make_float2(d[s][0], q0);
                float2 w1 = odd ? make_float2(q3, d[s][3]) : make_float2(d[s][2], q2);
                *(float2*)&Sg[(size_t)rowt * DIM + colt]     = w0;
                *(float2*)&Sg[(size_t)rowt * DIM + colt + 8] = w1;
            }
        } else if (2 * tg == (gr & ~1)) {
            // Sigma diagonal for kl
            int c = gr & 1;
            smf[OFF_DIAG + m0 + gr]     = d[0][c];
            smf[OFF_DIAG + m0 + gr + 8] = d[1][2 + c];
        }
    }

    // ---- phase 2b: sample = mean + L*eps (2 threads per row) ----
    {
        const int u = tid >> 1, h = tid & 1;
        const int r = (u & 1) ? (127 - (u >> 1)) : (u >> 1);
        const int c4tot = (r >> 2) + 1;
        const int ch0   = (c4tot + 1) >> 1;
        const int cbeg  = h ? ch0 : 0;
        const int cend  = h ? c4tot : ch0;
        const int rbase = rowbase(r);
        float dot = 0.0f;
        for (int c = cbeg; c < cend; c++) {
            const int j0 = c << 2;
            float4 lv = *(const float4*)&smf[rbase + j0];
            float4 ev = *(const float4*)&smf[OFF_EPS + j0];
            dot = fmaf(lv.x, ev.x, dot);
            dot = fmaf(lv.y, ev.y, dot);
            dot = fmaf(lv.z, ev.z, dot);
            dot = fmaf(lv.w, ev.w, dot);
        }
        dot += __shfl_xor_sync(0xffffffffu, dot, 1);
        if (!h)
            sample[(size_t)b * DIM + r] = smf[OFF_MEAN + r] + dot;
    }
    __syncthreads();   // s_diag / s_ld complete

    // ---- phase 3: kl (warp 0) ----
    if (wid == 0) {
        float t = 0.0f;
        #pragma unroll
        for (int k = 0; k < 4; k++) {
            int rr = lid + 32 * k;
            float m = smf[OFF_MEAN + rr];
            t += smf[OFF_DIAG + rr] - 1.0f + m * m - 2.0f * smf[OFF_LD + rr];
        }
        #pragma unroll
        for (int o = 16; o > 0; o >>= 1)
            t += __shfl_down_sync(0xffffffffu, t, o);
        if (lid == 0) kl[b] = 0.5f * t;
    }
}

extern "C" void kernel_launch(void* const* d_in, const int* in_sizes, int n_in,
                              void* d_out, int out_size)
{
    const float* params = (const float*)d_in[0];
    const float* eps    = (const float*)d_in[1];
    const int B = in_sizes[0] / NPARAMS;

    float* out    = (float*)d_out;
    float* sample = out;                       // B * 128
    float* kl     = out + (size_t)B * DIM;     // B
    float* sigma  = kl + B;                    // B * 128 * 128

    const int smem = SMEM_FLOATS * sizeof(float);
    cudaFuncSetAttribute(fld_mma_kernel,
                         cudaFuncAttributeMaxDynamicSharedMemorySize, smem);
    fld_mma_kernel<<<B, NT, smem>>>(params, eps, sample, kl, sigma);
}